// round 7
// baseline (speedup 1.0000x reference)
#include <cuda_runtime.h>

// Problem dims (fixed by reference)
#define BROWS 8192
#define DIN   256
#define NH1   512
#define NH2   256
#define DOUT  64

#define THRESHOLD 0.9f
#define NSPLIT 4
#define SEG (BROWS / NSPLIT)   // 2048
#define JT 64

typedef unsigned long long u64;

// Scratch (no cudaMalloc allowed)
__device__ float g_h1[BROWS * NH1];
__device__ float g_h2[BROWS * NH2];
__device__ float g_out[BROWS * DOUT];
__device__ float g_normed[BROWS * DOUT];

// ---------------------------------------------------------------------------
// packed fp32x2 helpers (sm_103a FFMA2 path; 2x fp32 FMA throughput)
// ---------------------------------------------------------------------------
__device__ __forceinline__ u64 fma2(u64 a, u64 b, u64 c) {
    u64 d;
    asm("fma.rn.f32x2 %0, %1, %2, %3;" : "=l"(d) : "l"(a), "l"(b), "l"(c));
    return d;
}
__device__ __forceinline__ u64 add2(u64 a, u64 b) {
    u64 d;
    asm("add.rn.f32x2 %0, %1, %2;" : "=l"(d) : "l"(a), "l"(b));
    return d;
}
__device__ __forceinline__ u64 pack2(float lo, float hi) {
    u64 d;
    asm("mov.b64 %0, {%1, %2};" : "=l"(d) : "f"(lo), "f"(hi));
    return d;
}
__device__ __forceinline__ float lo32(u64 v) { return __uint_as_float((unsigned)(v & 0xffffffffu)); }
__device__ __forceinline__ float hi32(u64 v) { return __uint_as_float((unsigned)(v >> 32)); }

// ---------------------------------------------------------------------------
// GEMM (NT) body with f32x2-packed N: C = tanh(A[M,K] @ W[N,K]^T + b)
// BM=BN=64, BK=16, 256 threads, per-thread 4i x 4j (as 4i x 2 packed pairs)
// ---------------------------------------------------------------------------
template<int N, int K>
__device__ __forceinline__ void gemm_nt_tanh_body(const float* __restrict__ A,
                                                  const float* __restrict__ W,
                                                  const float* __restrict__ bias,
                                                  float* __restrict__ C) {
    __shared__ float As[16][68];
    __shared__ float Ws[16][68];
    const int tid = threadIdx.x;
    const int tx = tid & 15, ty = tid >> 4;
    const int bm = blockIdx.y * 64, bn = blockIdx.x * 64;
    const int lr = tid >> 2;          // 0..63 row of tile
    const int lc = (tid & 3) << 2;    // 0,4,8,12 (float4 col)

    const float* Ag = A + (size_t)(bm + lr) * K + lc;
    const float* Wg = W + (size_t)(bn + lr) * K + lc;

    u64 acc[4][2] = {};
    for (int k0 = 0; k0 < K; k0 += 16) {
        float4 av = *(const float4*)(Ag + k0);
        float4 wv = *(const float4*)(Wg + k0);
        As[lc + 0][lr] = av.x; As[lc + 1][lr] = av.y;
        As[lc + 2][lr] = av.z; As[lc + 3][lr] = av.w;
        Ws[lc + 0][lr] = wv.x; Ws[lc + 1][lr] = wv.y;
        Ws[lc + 2][lr] = wv.z; Ws[lc + 3][lr] = wv.w;
        __syncthreads();
        #pragma unroll
        for (int k = 0; k < 16; k++) {
            float4 a4 = *(const float4*)&As[k][ty << 2];
            float4 w4 = *(const float4*)&Ws[k][tx << 2];
            const u64 wlo = pack2(w4.x, w4.y);
            const u64 whi = pack2(w4.z, w4.w);
            float a[4] = {a4.x, a4.y, a4.z, a4.w};
            #pragma unroll
            for (int i2 = 0; i2 < 4; i2++) {
                const u64 aa = pack2(a[i2], a[i2]);
                acc[i2][0] = fma2(aa, wlo, acc[i2][0]);
                acc[i2][1] = fma2(aa, whi, acc[i2][1]);
            }
        }
        __syncthreads();
    }
    const int colb = bn + (tx << 2);
    const float bb0 = bias[colb + 0], bb1 = bias[colb + 1];
    const float bb2 = bias[colb + 2], bb3 = bias[colb + 3];
    #pragma unroll
    for (int i2 = 0; i2 < 4; i2++) {
        const int row = bm + (ty << 2) + i2;
        float* cp = C + (size_t)row * N + colb;
        cp[0] = tanhf(lo32(acc[i2][0]) + bb0);
        cp[1] = tanhf(hi32(acc[i2][0]) + bb1);
        cp[2] = tanhf(lo32(acc[i2][1]) + bb2);
        cp[3] = tanhf(hi32(acc[i2][1]) + bb3);
    }
}

__global__ void gemm_l1(const float* __restrict__ x,
                        const float* __restrict__ W1,
                        const float* __restrict__ b1) {
    gemm_nt_tanh_body<NH1, DIN>(x, W1, b1, g_h1);
}
__global__ void gemm_l2(const float* __restrict__ W2,
                        const float* __restrict__ b2) {
    gemm_nt_tanh_body<NH2, NH1>(g_h1, W2, b2, g_h2);
}

// ---------------------------------------------------------------------------
// Final linear (no tanh) + per-row L2 norm epilogue -> g_out, g_normed
// N = 64 (full width in one block tile), K = 256, A = g_h2
// ---------------------------------------------------------------------------
__global__ void gemm_out_norm(const float* __restrict__ W,
                              const float* __restrict__ bias) {
    __shared__ float As[16][68];
    __shared__ float Ws[16][68];
    __shared__ float Cs[64][65];
    const int tid = threadIdx.x;
    const int tx = tid & 15, ty = tid >> 4;
    const int bm = blockIdx.x * 64;
    const int lr = tid >> 2;
    const int lc = (tid & 3) << 2;

    const float* Ag = g_h2 + (size_t)(bm + lr) * 256 + lc;
    const float* Wg = W + (size_t)lr * 256 + lc;   // W3 is [64,256]

    u64 acc[4][2] = {};
    for (int k0 = 0; k0 < 256; k0 += 16) {
        float4 av = *(const float4*)(Ag + k0);
        float4 wv = *(const float4*)(Wg + k0);
        As[lc + 0][lr] = av.x; As[lc + 1][lr] = av.y;
        As[lc + 2][lr] = av.z; As[lc + 3][lr] = av.w;
        Ws[lc + 0][lr] = wv.x; Ws[lc + 1][lr] = wv.y;
        Ws[lc + 2][lr] = wv.z; Ws[lc + 3][lr] = wv.w;
        __syncthreads();
        #pragma unroll
        for (int k = 0; k < 16; k++) {
            float4 a4 = *(const float4*)&As[k][ty << 2];
            float4 w4 = *(const float4*)&Ws[k][tx << 2];
            const u64 wlo = pack2(w4.x, w4.y);
            const u64 whi = pack2(w4.z, w4.w);
            float a[4] = {a4.x, a4.y, a4.z, a4.w};
            #pragma unroll
            for (int i2 = 0; i2 < 4; i2++) {
                const u64 aa = pack2(a[i2], a[i2]);
                acc[i2][0] = fma2(aa, wlo, acc[i2][0]);
                acc[i2][1] = fma2(aa, whi, acc[i2][1]);
            }
        }
        __syncthreads();
    }
    const int colb = tx << 2;
    #pragma unroll
    for (int i2 = 0; i2 < 4; i2++) {
        const int r = (ty << 2) + i2;
        Cs[r][colb + 0] = lo32(acc[i2][0]) + bias[colb + 0];
        Cs[r][colb + 1] = hi32(acc[i2][0]) + bias[colb + 1];
        Cs[r][colb + 2] = lo32(acc[i2][1]) + bias[colb + 2];
        Cs[r][colb + 3] = hi32(acc[i2][1]) + bias[colb + 3];
    }
    __syncthreads();

    const int warp = tid >> 5, lane = tid & 31;
    #pragma unroll
    for (int r8 = 0; r8 < 8; r8++) {
        const int r = warp * 8 + r8;
        const float v0 = Cs[r][lane];
        const float v1 = Cs[r][lane + 32];
        float s = v0 * v0 + v1 * v1;
        #pragma unroll
        for (int off = 16; off; off >>= 1)
            s += __shfl_xor_sync(0xffffffffu, s, off);
        const float inv = 1.0f / (sqrtf(s) + 1e-12f);
        const size_t base = (size_t)(bm + r) * 64;
        g_out[base + lane]        = v0;
        g_out[base + lane + 32]   = v1;
        g_normed[base + lane]      = v0 * inv;
        g_normed[base + lane + 32] = v1 * inv;
    }
}

// ---------------------------------------------------------------------------
// y init: y[i] = -out[i]  (diagonal fid == 1 always passes threshold; the fid
// kernel adds out[i] unconditionally for j == i, this cancels it)
// ---------------------------------------------------------------------------
__global__ void init_y(float* __restrict__ y) {
    const int t = blockIdx.x * 256 + threadIdx.x;
    y[t] = -g_out[t];
}

// ---------------------------------------------------------------------------
// Fidelity + thresholded gather:  y[i] += sum_{(n_i.n_j)^2 >= 0.9} out[j]
// 4 threads per i-row (16 floats = 8 u64 each). 64 i per block, j split
// NSPLIT ways. Single-wave grid (512 blocks @ 4 blocks/SM).
// ---------------------------------------------------------------------------
__global__ void __launch_bounds__(256, 4) fid_gather(float* __restrict__ y) {
    __shared__ float sn[JT * 64];
    __shared__ float so[JT * 64];
    const int tid = threadIdx.x;
    const int i = blockIdx.x * 64 + (tid >> 2);
    const int q8 = (tid & 3) * 8;        // quarter offset in u64 units

    const u64* nip = (const u64*)(g_normed + (size_t)i * 64) + q8;
    u64 ni[8], acc[8];
    #pragma unroll
    for (int u = 0; u < 8; u++) { ni[u] = nip[u]; acc[u] = 0ull; }

    const int jbase0 = blockIdx.y * SEG;
    for (int t = 0; t < SEG; t += JT) {
        const int jb = jbase0 + t;
        {   // cooperative tile load: JT rows of normed + out (32 KB)
            const float4* gn = (const float4*)(g_normed + (size_t)jb * 64);
            const float4* go = (const float4*)(g_out + (size_t)jb * 64);
            float4* s4n = (float4*)sn;
            float4* s4o = (float4*)so;
            #pragma unroll
            for (int u = 0; u < 4; u++) {
                const int idx = tid + 256 * u;
                s4n[idx] = gn[idx];
                s4o[idx] = go[idx];
            }
        }
        __syncthreads();
        #pragma unroll 2
        for (int jj = 0; jj < JT; jj++) {
            const u64* nj = (const u64*)(sn + jj * 64) + q8;
            u64 p0 = 0ull, p1 = 0ull;
            #pragma unroll
            for (int u = 0; u < 4; u++) {
                p0 = fma2(ni[2 * u],     nj[2 * u],     p0);
                p1 = fma2(ni[2 * u + 1], nj[2 * u + 1], p1);
            }
            const u64 p = add2(p0, p1);
            float part = lo32(p) + hi32(p);
            part += __shfl_xor_sync(0xffffffffu, part, 1);
            part += __shfl_xor_sync(0xffffffffu, part, 2);
            if (part * part >= THRESHOLD) {
                const u64* oj = (const u64*)(so + jj * 64) + q8;
                #pragma unroll
                for (int u = 0; u < 8; u++) acc[u] = add2(acc[u], oj[u]);
            }
        }
        __syncthreads();
    }

    float* yp = y + (size_t)i * 64 + (tid & 3) * 16;
    #pragma unroll
    for (int u = 0; u < 8; u++) {
        atomicAdd(yp + 2 * u,     lo32(acc[u]));
        atomicAdd(yp + 2 * u + 1, hi32(acc[u]));
    }
}

// ---------------------------------------------------------------------------
extern "C" void kernel_launch(void* const* d_in, const int* in_sizes, int n_in,
                              void* d_out, int out_size) {
    const float* x  = (const float*)d_in[0];
    const float* W1 = (const float*)d_in[1];
    const float* b1 = (const float*)d_in[2];
    const float* W2 = (const float*)d_in[3];
    const float* b2 = (const float*)d_in[4];
    const float* W3 = (const float*)d_in[5];
    const float* b3 = (const float*)d_in[6];
    float* y = (float*)d_out;

    // Layer 1: [8192,256] -> [8192,512], tanh
    gemm_l1<<<dim3(NH1 / 64, BROWS / 64), 256>>>(x, W1, b1);
    // Layer 2: [8192,512] -> [8192,256], tanh
    gemm_l2<<<dim3(NH2 / 64, BROWS / 64), 256>>>(W2, b2);
    // Layer 3 + row norms -> g_out, g_normed
    gemm_out_norm<<<BROWS / 64, 256>>>(W3, b3);
    // y = -out (cancels diagonal contribution added by fid)
    init_y<<<(BROWS * DOUT) / 256, 256>>>(y);
    // Fidelity adjacency gather
    fid_gather<<<dim3(BROWS / 64, NSPLIT), 256>>>(y);
}

// round 8
// speedup vs baseline: 4.3697x; 4.3697x over previous
#include <cuda_runtime.h>

// Problem dims (fixed by reference)
#define BROWS 8192
#define DIN   256
#define NH1   512
#define NH2   256
#define DOUT  64

// Fidelity threshold: pass iff dot^2 >= 0.9  <=>  |dot| >= sqrt(0.9)
#define S_LO 0.9447f   // sure-fail below (sqrt(0.9) - 4e-3 guard)
#define S_HI 0.9527f   // sure-pass above (sqrt(0.9) + 4e-3 guard)

#define FNS  8                 // j-range splits
#define FSEG (BROWS / FNS)     // 1024
#define FJT  64                // j-chunk rows in smem

// Scratch (no cudaMalloc allowed)
__device__ float g_h1[BROWS * NH1];
__device__ float g_h2[BROWS * NH2];
__device__ float g_out[BROWS * DOUT];
__device__ float g_normed[BROWS * DOUT];

// ---------------------------------------------------------------------------
// Scalar GEMM (NT): C = tanh(A[M,K] @ W[N,K]^T + b). BM=BN=64, BK=16, 256 thr
// (known-good 741us version — f32x2 path measured 2x slower, reverted)
// ---------------------------------------------------------------------------
template<int N, int K>
__device__ __forceinline__ void gemm_nt_tanh_body(const float* __restrict__ A,
                                                  const float* __restrict__ W,
                                                  const float* __restrict__ bias,
                                                  float* __restrict__ C) {
    __shared__ float As[16][68];
    __shared__ float Ws[16][68];
    const int tid = threadIdx.x;
    const int tx = tid & 15, ty = tid >> 4;
    const int bm = blockIdx.y * 64, bn = blockIdx.x * 64;
    const int lr = tid >> 2;
    const int lc = (tid & 3) << 2;

    const float* Ag = A + (size_t)(bm + lr) * K + lc;
    const float* Wg = W + (size_t)(bn + lr) * K + lc;

    float acc[4][4] = {};
    for (int k0 = 0; k0 < K; k0 += 16) {
        float4 av = *(const float4*)(Ag + k0);
        float4 wv = *(const float4*)(Wg + k0);
        As[lc + 0][lr] = av.x; As[lc + 1][lr] = av.y;
        As[lc + 2][lr] = av.z; As[lc + 3][lr] = av.w;
        Ws[lc + 0][lr] = wv.x; Ws[lc + 1][lr] = wv.y;
        Ws[lc + 2][lr] = wv.z; Ws[lc + 3][lr] = wv.w;
        __syncthreads();
        #pragma unroll
        for (int k = 0; k < 16; k++) {
            float4 a4 = *(const float4*)&As[k][ty << 2];
            float4 w4 = *(const float4*)&Ws[k][tx << 2];
            float a[4] = {a4.x, a4.y, a4.z, a4.w};
            float w[4] = {w4.x, w4.y, w4.z, w4.w};
            #pragma unroll
            for (int i2 = 0; i2 < 4; i2++)
                #pragma unroll
                for (int j2 = 0; j2 < 4; j2++)
                    acc[i2][j2] = fmaf(a[i2], w[j2], acc[i2][j2]);
        }
        __syncthreads();
    }
    #pragma unroll
    for (int i2 = 0; i2 < 4; i2++) {
        const int row = bm + (ty << 2) + i2;
        #pragma unroll
        for (int j2 = 0; j2 < 4; j2++) {
            const int col = bn + (tx << 2) + j2;
            C[(size_t)row * N + col] = tanhf(acc[i2][j2] + bias[col]);
        }
    }
}

__global__ void gemm_l1(const float* __restrict__ x,
                        const float* __restrict__ W1,
                        const float* __restrict__ b1) {
    gemm_nt_tanh_body<NH1, DIN>(x, W1, b1, g_h1);
}
__global__ void gemm_l2(const float* __restrict__ W2,
                        const float* __restrict__ b2) {
    gemm_nt_tanh_body<NH2, NH1>(g_h1, W2, b2, g_h2);
}

// ---------------------------------------------------------------------------
// Final linear (no tanh) + per-row L2 norm -> g_out, g_normed (scalar, exact)
// ---------------------------------------------------------------------------
__global__ void gemm_out_norm(const float* __restrict__ W,
                              const float* __restrict__ bias) {
    __shared__ float As[16][68];
    __shared__ float Ws[16][68];
    __shared__ float Cs[64][65];
    const int tid = threadIdx.x;
    const int tx = tid & 15, ty = tid >> 4;
    const int bm = blockIdx.x * 64;
    const int lr = tid >> 2;
    const int lc = (tid & 3) << 2;

    const float* Ag = g_h2 + (size_t)(bm + lr) * 256 + lc;
    const float* Wg = W + (size_t)lr * 256 + lc;   // W3 is [64,256]

    float acc[4][4] = {};
    for (int k0 = 0; k0 < 256; k0 += 16) {
        float4 av = *(const float4*)(Ag + k0);
        float4 wv = *(const float4*)(Wg + k0);
        As[lc + 0][lr] = av.x; As[lc + 1][lr] = av.y;
        As[lc + 2][lr] = av.z; As[lc + 3][lr] = av.w;
        Ws[lc + 0][lr] = wv.x; Ws[lc + 1][lr] = wv.y;
        Ws[lc + 2][lr] = wv.z; Ws[lc + 3][lr] = wv.w;
        __syncthreads();
        #pragma unroll
        for (int k = 0; k < 16; k++) {
            float4 a4 = *(const float4*)&As[k][ty << 2];
            float4 w4 = *(const float4*)&Ws[k][tx << 2];
            float a[4] = {a4.x, a4.y, a4.z, a4.w};
            float w[4] = {w4.x, w4.y, w4.z, w4.w};
            #pragma unroll
            for (int i2 = 0; i2 < 4; i2++)
                #pragma unroll
                for (int j2 = 0; j2 < 4; j2++)
                    acc[i2][j2] = fmaf(a[i2], w[j2], acc[i2][j2]);
        }
        __syncthreads();
    }
    #pragma unroll
    for (int i2 = 0; i2 < 4; i2++)
        #pragma unroll
        for (int j2 = 0; j2 < 4; j2++)
            Cs[(ty << 2) + i2][(tx << 2) + j2] = acc[i2][j2] + bias[(tx << 2) + j2];
    __syncthreads();

    const int warp = tid >> 5, lane = tid & 31;
    #pragma unroll
    for (int r8 = 0; r8 < 8; r8++) {
        const int r = warp * 8 + r8;
        const float v0 = Cs[r][lane];
        const float v1 = Cs[r][lane + 32];
        float s = v0 * v0 + v1 * v1;
        #pragma unroll
        for (int off = 16; off; off >>= 1)
            s += __shfl_xor_sync(0xffffffffu, s, off);
        const float inv = 1.0f / (sqrtf(s) + 1e-12f);
        const size_t base = (size_t)(bm + r) * 64;
        g_out[base + lane]        = v0;
        g_out[base + lane + 32]   = v1;
        g_normed[base + lane]      = v0 * inv;
        g_normed[base + lane + 32] = v1 * inv;
    }
}

// y init: y[i] = -out[i]  (diag fid == 1 is a sure-pass in fid_mma; cancels)
__global__ void init_y(float* __restrict__ y) {
    const int t = blockIdx.x * 256 + threadIdx.x;
    y[t] = -g_out[t];
}

// ---------------------------------------------------------------------------
// tf32 tensor-core helpers
// ---------------------------------------------------------------------------
__device__ __forceinline__ unsigned to_tf32(float f) {
    unsigned u;
    asm("cvt.rna.tf32.f32 %0, %1;" : "=r"(u) : "f"(f));
    return u;
}
__device__ __forceinline__ void mma_tf32(float d[4], const unsigned a[4],
                                         const unsigned b[2]) {
    asm volatile(
        "mma.sync.aligned.m16n8k8.row.col.f32.tf32.tf32.f32 "
        "{%0,%1,%2,%3}, {%4,%5,%6,%7}, {%8,%9}, {%0,%1,%2,%3};"
        : "+f"(d[0]), "+f"(d[1]), "+f"(d[2]), "+f"(d[3])
        : "r"(a[0]), "r"(a[1]), "r"(a[2]), "r"(a[3]), "r"(b[0]), "r"(b[1]));
}

// ---------------------------------------------------------------------------
// Fidelity via tf32 MMA + rigorous fp32 guard-band recheck.
// Block: 128 i-rows (8 warps x m16). A-frags resident. j-chunks of 64 in smem.
// normed rows are unit vectors => |tf32_dot - fp32_dot| <= ~1.1e-3 (Cauchy-
// Schwarz on input rounding), so [S_LO, S_HI) is the only ambiguous band.
// ---------------------------------------------------------------------------
__global__ void __launch_bounds__(256) fid_mma(float* __restrict__ y) {
    __shared__ float sn[FJT * 68];   // normed_j, row stride 68 (conflict-free)
    __shared__ float so[FJT * 64];   // out_j
    const int tid = threadIdx.x;
    const int w = tid >> 5, lane = tid & 31;
    const int g = lane >> 2, t = lane & 3;
    const int i0 = blockIdx.x * 128 + w * 16;   // warp's 16 i-rows

    // A fragments: m16 x k64 (8 k-steps), loaded once, reused for all j
    unsigned a[8][4];
    {
        const float* base = g_normed + (size_t)i0 * 64;
        #pragma unroll
        for (int kk = 0; kk < 8; kk++) {
            a[kk][0] = to_tf32(base[(size_t)g * 64 + kk * 8 + t]);
            a[kk][1] = to_tf32(base[(size_t)(g + 8) * 64 + kk * 8 + t]);
            a[kk][2] = to_tf32(base[(size_t)g * 64 + kk * 8 + t + 4]);
            a[kk][3] = to_tf32(base[(size_t)(g + 8) * 64 + kk * 8 + t + 4]);
        }
    }

    const int jb0 = blockIdx.y * FSEG;
    for (int jc = 0; jc < FSEG; jc += FJT) {
        const int jb = jb0 + jc;
        {   // cooperative chunk load (64 rows of normed + out)
            const float4* gn = (const float4*)(g_normed + (size_t)jb * 64);
            const float4* go = (const float4*)(g_out + (size_t)jb * 64);
            #pragma unroll
            for (int u = 0; u < 4; u++) {
                const int idx = tid + 256 * u;          // 0..1023 float4s
                const int row = idx >> 4, c4 = idx & 15;
                ((float4*)sn)[row * 17 + c4] = gn[idx]; // stride 68 floats
                ((float4*)so)[idx] = go[idx];
            }
        }
        __syncthreads();

        #pragma unroll
        for (int np = 0; np < 4; np++) {     // 2 interleaved n8 tiles per pass
            const int n0 = np * 16;
            float d0[4] = {0.f, 0.f, 0.f, 0.f};
            float d1[4] = {0.f, 0.f, 0.f, 0.f};
            #pragma unroll
            for (int kk = 0; kk < 8; kk++) {
                unsigned b0[2], b1[2];
                const int ka = kk * 8 + t;
                b0[0] = to_tf32(sn[(n0 + g) * 68 + ka]);
                b0[1] = to_tf32(sn[(n0 + g) * 68 + ka + 4]);
                b1[0] = to_tf32(sn[(n0 + 8 + g) * 68 + ka]);
                b1[1] = to_tf32(sn[(n0 + 8 + g) * 68 + ka + 4]);
                mma_tf32(d0, a[kk], b0);
                mma_tf32(d1, a[kk], b1);
            }
            // classify + gather. d[q] maps to (row, col):
            //   q0:(g, 2t) q1:(g, 2t+1) q2:(g+8, 2t) q3:(g+8, 2t+1)
            #pragma unroll
            for (int half = 0; half < 2; half++) {
                const float* dd = half ? d1 : d0;
                const int nb = n0 + half * 8;           // local j base of tile
                #pragma unroll
                for (int q = 0; q < 4; q++) {
                    const float ad = fabsf(dd[q]);
                    if (ad < S_LO) continue;            // common case
                    const int ri = i0 + g + (q >> 1) * 8;
                    const int jl = nb + 2 * t + (q & 1);
                    bool pass = true;
                    if (ad < S_HI) {                    // ambiguous: fp32 recheck
                        const float* ni = g_normed + (size_t)ri * 64;
                        const float* nj = sn + jl * 68;
                        float s = 0.f;
                        #pragma unroll 8
                        for (int k = 0; k < 64; k++) s = fmaf(ni[k], nj[k], s);
                        pass = (s * s >= 0.9f);
                    }
                    if (pass) {
                        const float* oj = so + jl * 64;
                        float* yp = y + (size_t)ri * 64;
                        #pragma unroll 8
                        for (int u = 0; u < 64; u++) atomicAdd(yp + u, oj[u]);
                    }
                }
            }
        }
        __syncthreads();
    }
}

// ---------------------------------------------------------------------------
extern "C" void kernel_launch(void* const* d_in, const int* in_sizes, int n_in,
                              void* d_out, int out_size) {
    const float* x  = (const float*)d_in[0];
    const float* W1 = (const float*)d_in[1];
    const float* b1 = (const float*)d_in[2];
    const float* W2 = (const float*)d_in[3];
    const float* b2 = (const float*)d_in[4];
    const float* W3 = (const float*)d_in[5];
    const float* b3 = (const float*)d_in[6];
    float* y = (float*)d_out;

    gemm_l1<<<dim3(NH1 / 64, BROWS / 64), 256>>>(x, W1, b1);
    gemm_l2<<<dim3(NH2 / 64, BROWS / 64), 256>>>(W2, b2);
    gemm_out_norm<<<BROWS / 64, 256>>>(W3, b3);
    init_y<<<(BROWS * DOUT) / 256, 256>>>(y);
    fid_mma<<<dim3(BROWS / 128, FNS), 256>>>(y);
}

// round 9
// speedup vs baseline: 6.2877x; 1.4389x over previous
#include <cuda_runtime.h>

// Problem dims (fixed by reference)
#define BROWS 8192
#define DIN   256
#define NH1   512
#define NH2   256
#define DOUT  64

// Fidelity threshold: pass iff dot^2 >= 0.9  <=>  |dot| >= sqrt(0.9)
#define S_LO 0.9447f   // sure-fail below (sqrt(0.9) - 4e-3 guard)
#define S_HI 0.9527f   // sure-pass above (sqrt(0.9) + 4e-3 guard)

#define FNS  8                 // j-range splits
#define FSEG (BROWS / FNS)     // 1024
#define FJT  64                // j-chunk rows in smem

// Scratch (no cudaMalloc allowed)
__device__ float g_h1[BROWS * NH1];
__device__ float g_h2[BROWS * NH2];
__device__ float g_out[BROWS * DOUT];
__device__ float g_normed[BROWS * DOUT];

// ---------------------------------------------------------------------------
// tf32 tensor-core helpers
// ---------------------------------------------------------------------------
__device__ __forceinline__ unsigned to_tf32(float f) {
    unsigned u;
    asm("cvt.rna.tf32.f32 %0, %1;" : "=r"(u) : "f"(f));
    return u;
}
__device__ __forceinline__ void mma_tf32(float d[4], const unsigned a[4],
                                         const unsigned b[2]) {
    asm volatile(
        "mma.sync.aligned.m16n8k8.row.col.f32.tf32.tf32.f32 "
        "{%0,%1,%2,%3}, {%4,%5,%6,%7}, {%8,%9}, {%0,%1,%2,%3};"
        : "+f"(d[0]), "+f"(d[1]), "+f"(d[2]), "+f"(d[3])
        : "r"(a[0]), "r"(a[1]), "r"(a[2]), "r"(a[3]), "r"(b[0]), "r"(b[1]));
}

// ---------------------------------------------------------------------------
// tf32 MMA GEMM (NT): C = tanh(A[M,K] @ W[N,K]^T + b)
// BM=128, BN=64, BK=32, 256 threads, warp grid 4m x 2n (32x32 per warp).
// Floats converted to tf32 bits once at gmem->smem store; stride-36 smem
// rows make A/B fragment LDS conflict-free.
// ---------------------------------------------------------------------------
template<int N, int K>
__device__ __forceinline__ void gemm_tf32_tanh_body(const float* __restrict__ A,
                                                    const float* __restrict__ W,
                                                    const float* __restrict__ bias,
                                                    float* __restrict__ C) {
    __shared__ unsigned As[128 * 36];
    __shared__ unsigned Bs[64 * 36];
    const int tid = threadIdx.x;
    const int w = tid >> 5, lane = tid & 31;
    const int g = lane >> 2, t = lane & 3;
    const int wm = (w & 3) * 32;      // warp m offset in tile
    const int wn = (w >> 2) * 32;     // warp n offset in tile
    const int bm = blockIdx.y * 128, bn = blockIdx.x * 64;

    float d[2][4][4] = {};            // [m frag][n frag][quad]

    for (int k0 = 0; k0 < K; k0 += 32) {
        // A tile: 128 rows x 32 cols = 1024 float4 loads, 4 per thread
        #pragma unroll
        for (int u = 0; u < 4; u++) {
            const int idx = tid + 256 * u;
            const int row = idx >> 3, c4 = (idx & 7) << 2;
            float4 v = *(const float4*)(A + (size_t)(bm + row) * K + k0 + c4);
            unsigned* s = As + row * 36 + c4;
            s[0] = to_tf32(v.x); s[1] = to_tf32(v.y);
            s[2] = to_tf32(v.z); s[3] = to_tf32(v.w);
        }
        // B tile: 64 rows x 32 cols = 512 float4 loads, 2 per thread
        #pragma unroll
        for (int u = 0; u < 2; u++) {
            const int idx = tid + 256 * u;
            const int row = idx >> 3, c4 = (idx & 7) << 2;
            float4 v = *(const float4*)(W + (size_t)(bn + row) * K + k0 + c4);
            unsigned* s = Bs + row * 36 + c4;
            s[0] = to_tf32(v.x); s[1] = to_tf32(v.y);
            s[2] = to_tf32(v.z); s[3] = to_tf32(v.w);
        }
        __syncthreads();

        #pragma unroll
        for (int kk = 0; kk < 4; kk++) {
            const int ka = kk * 8 + t;
            unsigned a[2][4];
            #pragma unroll
            for (int mi = 0; mi < 2; mi++) {
                const unsigned* ab = As + (wm + mi * 16) * 36;
                a[mi][0] = ab[(size_t)g * 36 + ka];
                a[mi][1] = ab[(size_t)(g + 8) * 36 + ka];
                a[mi][2] = ab[(size_t)g * 36 + ka + 4];
                a[mi][3] = ab[(size_t)(g + 8) * 36 + ka + 4];
            }
            #pragma unroll
            for (int ni = 0; ni < 4; ni++) {
                unsigned b[2];
                const unsigned* bb = Bs + (wn + ni * 8 + g) * 36;
                b[0] = bb[ka];
                b[1] = bb[ka + 4];
                mma_tf32(d[0][ni], a[0], b);
                mma_tf32(d[1][ni], a[1], b);
            }
        }
        __syncthreads();
    }

    // epilogue: bias + tanh, direct store
    #pragma unroll
    for (int mi = 0; mi < 2; mi++) {
        #pragma unroll
        for (int ni = 0; ni < 4; ni++) {
            const int colb = bn + wn + ni * 8 + 2 * t;
            const float bb0 = bias[colb], bb1 = bias[colb + 1];
            #pragma unroll
            for (int h = 0; h < 2; h++) {     // q pairs: rows g, g+8
                const int row = bm + wm + mi * 16 + g + h * 8;
                float* cp = C + (size_t)row * N + colb;
                cp[0] = tanhf(d[mi][ni][2 * h] + bb0);
                cp[1] = tanhf(d[mi][ni][2 * h + 1] + bb1);
            }
        }
    }
}

__global__ void __launch_bounds__(256) gemm_l1(const float* __restrict__ x,
                                               const float* __restrict__ W1,
                                               const float* __restrict__ b1) {
    gemm_tf32_tanh_body<NH1, DIN>(x, W1, b1, g_h1);
}
__global__ void __launch_bounds__(256) gemm_l2(const float* __restrict__ W2,
                                               const float* __restrict__ b2) {
    gemm_tf32_tanh_body<NH2, NH1>(g_h1, W2, b2, g_h2);
}

// ---------------------------------------------------------------------------
// Final linear (no tanh) + per-row L2 norm -> g_out, g_normed
// (exact scalar fp32 — keeps out/normed at full precision)
// ---------------------------------------------------------------------------
__global__ void gemm_out_norm(const float* __restrict__ W,
                              const float* __restrict__ bias) {
    __shared__ float As[16][68];
    __shared__ float Ws[16][68];
    __shared__ float Cs[64][65];
    const int tid = threadIdx.x;
    const int tx = tid & 15, ty = tid >> 4;
    const int bm = blockIdx.x * 64;
    const int lr = tid >> 2;
    const int lc = (tid & 3) << 2;

    const float* Ag = g_h2 + (size_t)(bm + lr) * 256 + lc;
    const float* Wg = W + (size_t)lr * 256 + lc;   // W3 is [64,256]

    float acc[4][4] = {};
    for (int k0 = 0; k0 < 256; k0 += 16) {
        float4 av = *(const float4*)(Ag + k0);
        float4 wv = *(const float4*)(Wg + k0);
        As[lc + 0][lr] = av.x; As[lc + 1][lr] = av.y;
        As[lc + 2][lr] = av.z; As[lc + 3][lr] = av.w;
        Ws[lc + 0][lr] = wv.x; Ws[lc + 1][lr] = wv.y;
        Ws[lc + 2][lr] = wv.z; Ws[lc + 3][lr] = wv.w;
        __syncthreads();
        #pragma unroll
        for (int k = 0; k < 16; k++) {
            float4 a4 = *(const float4*)&As[k][ty << 2];
            float4 w4 = *(const float4*)&Ws[k][tx << 2];
            float a[4] = {a4.x, a4.y, a4.z, a4.w};
            float ww[4] = {w4.x, w4.y, w4.z, w4.w};
            #pragma unroll
            for (int i2 = 0; i2 < 4; i2++)
                #pragma unroll
                for (int j2 = 0; j2 < 4; j2++)
                    acc[i2][j2] = fmaf(a[i2], ww[j2], acc[i2][j2]);
        }
        __syncthreads();
    }
    #pragma unroll
    for (int i2 = 0; i2 < 4; i2++)
        #pragma unroll
        for (int j2 = 0; j2 < 4; j2++)
            Cs[(ty << 2) + i2][(tx << 2) + j2] = acc[i2][j2] + bias[(tx << 2) + j2];
    __syncthreads();

    const int warp = tid >> 5, lane = tid & 31;
    #pragma unroll
    for (int r8 = 0; r8 < 8; r8++) {
        const int r = warp * 8 + r8;
        const float v0 = Cs[r][lane];
        const float v1 = Cs[r][lane + 32];
        float s = v0 * v0 + v1 * v1;
        #pragma unroll
        for (int off = 16; off; off >>= 1)
            s += __shfl_xor_sync(0xffffffffu, s, off);
        const float inv = 1.0f / (sqrtf(s) + 1e-12f);
        const size_t base = (size_t)(bm + r) * 64;
        g_out[base + lane]        = v0;
        g_out[base + lane + 32]   = v1;
        g_normed[base + lane]      = v0 * inv;
        g_normed[base + lane + 32] = v1 * inv;
    }
}

// y init: y[i] = -out[i]  (diag fid == 1 is a sure-pass in fid_mma; cancels)
__global__ void init_y(float* __restrict__ y) {
    const int t = blockIdx.x * 256 + threadIdx.x;
    y[t] = -g_out[t];
}

// ---------------------------------------------------------------------------
// Fidelity via tf32 MMA + rigorous fp32 guard-band recheck. (unchanged)
// ---------------------------------------------------------------------------
__global__ void __launch_bounds__(256) fid_mma(float* __restrict__ y) {
    __shared__ float sn[FJT * 68];   // normed_j, row stride 68 (conflict-free)
    __shared__ float so[FJT * 64];   // out_j
    const int tid = threadIdx.x;
    const int w = tid >> 5, lane = tid & 31;
    const int g = lane >> 2, t = lane & 3;
    const int i0 = blockIdx.x * 128 + w * 16;   // warp's 16 i-rows

    unsigned a[8][4];
    {
        const float* base = g_normed + (size_t)i0 * 64;
        #pragma unroll
        for (int kk = 0; kk < 8; kk++) {
            a[kk][0] = to_tf32(base[(size_t)g * 64 + kk * 8 + t]);
            a[kk][1] = to_tf32(base[(size_t)(g + 8) * 64 + kk * 8 + t]);
            a[kk][2] = to_tf32(base[(size_t)g * 64 + kk * 8 + t + 4]);
            a[kk][3] = to_tf32(base[(size_t)(g + 8) * 64 + kk * 8 + t + 4]);
        }
    }

    const int jb0 = blockIdx.y * FSEG;
    for (int jc = 0; jc < FSEG; jc += FJT) {
        const int jb = jb0 + jc;
        {   // cooperative chunk load (64 rows of normed + out)
            const float4* gn = (const float4*)(g_normed + (size_t)jb * 64);
            const float4* go = (const float4*)(g_out + (size_t)jb * 64);
            #pragma unroll
            for (int u = 0; u < 4; u++) {
                const int idx = tid + 256 * u;          // 0..1023 float4s
                const int row = idx >> 4, c4 = idx & 15;
                ((float4*)sn)[row * 17 + c4] = gn[idx]; // stride 68 floats
                ((float4*)so)[idx] = go[idx];
            }
        }
        __syncthreads();

        #pragma unroll
        for (int np = 0; np < 4; np++) {
            const int n0 = np * 16;
            float d0[4] = {0.f, 0.f, 0.f, 0.f};
            float d1[4] = {0.f, 0.f, 0.f, 0.f};
            #pragma unroll
            for (int kk = 0; kk < 8; kk++) {
                unsigned b0[2], b1[2];
                const int ka = kk * 8 + t;
                b0[0] = to_tf32(sn[(n0 + g) * 68 + ka]);
                b0[1] = to_tf32(sn[(n0 + g) * 68 + ka + 4]);
                b1[0] = to_tf32(sn[(n0 + 8 + g) * 68 + ka]);
                b1[1] = to_tf32(sn[(n0 + 8 + g) * 68 + ka + 4]);
                mma_tf32(d0, a[kk], b0);
                mma_tf32(d1, a[kk], b1);
            }
            #pragma unroll
            for (int half = 0; half < 2; half++) {
                const float* dd = half ? d1 : d0;
                const int nb = n0 + half * 8;
                #pragma unroll
                for (int q = 0; q < 4; q++) {
                    const float ad = fabsf(dd[q]);
                    if (ad < S_LO) continue;            // common case
                    const int ri = i0 + g + (q >> 1) * 8;
                    const int jl = nb + 2 * t + (q & 1);
                    bool pass = true;
                    if (ad < S_HI) {                    // ambiguous: fp32 recheck
                        const float* ni = g_normed + (size_t)ri * 64;
                        const float* nj = sn + jl * 68;
                        float s = 0.f;
                        #pragma unroll 8
                        for (int k = 0; k < 64; k++) s = fmaf(ni[k], nj[k], s);
                        pass = (s * s >= 0.9f);
                    }
                    if (pass) {
                        const float* oj = so + jl * 64;
                        float* yp = y + (size_t)ri * 64;
                        #pragma unroll 8
                        for (int u = 0; u < 64; u++) atomicAdd(yp + u, oj[u]);
                    }
                }
            }
        }
        __syncthreads();
    }
}

// ---------------------------------------------------------------------------
extern "C" void kernel_launch(void* const* d_in, const int* in_sizes, int n_in,
                              void* d_out, int out_size) {
    const float* x  = (const float*)d_in[0];
    const float* W1 = (const float*)d_in[1];
    const float* b1 = (const float*)d_in[2];
    const float* W2 = (const float*)d_in[3];
    const float* b2 = (const float*)d_in[4];
    const float* W3 = (const float*)d_in[5];
    const float* b3 = (const float*)d_in[6];
    float* y = (float*)d_out;

    gemm_l1<<<dim3(NH1 / 64, BROWS / 128), 256>>>(x, W1, b1);
    gemm_l2<<<dim3(NH2 / 64, BROWS / 128), 256>>>(W2, b2);
    gemm_out_norm<<<BROWS / 64, 256>>>(W3, b3);
    init_y<<<(BROWS * DOUT) / 256, 256>>>(y);
    fid_mma<<<dim3(BROWS / 128, FNS), 256>>>(y);
}

// round 12
// speedup vs baseline: 7.1729x; 1.1408x over previous
#include <cuda_runtime.h>

// Problem dims (fixed by reference)
#define BROWS 8192
#define DIN   256
#define NH1   512
#define NH2   256
#define DOUT  64

// Fidelity threshold: pass iff dot^2 >= 0.9  <=>  |dot| >= sqrt(0.9)
#define S_LO 0.9447f   // sure-fail below (sqrt(0.9) - 4e-3 guard)
#define S_HI 0.9527f   // sure-pass above (sqrt(0.9) + 4e-3 guard)

#define FNS  8                 // j-range splits
#define FSEG (BROWS / FNS)     // 1024
#define FJT  64                // j-chunk rows in smem
#define SNS  72                // sn row stride in words (>=64; ==8 mod 32: bank-clean)

// Scratch (no cudaMalloc allowed)
__device__ float g_h1[BROWS * NH1];
__device__ float g_h2[BROWS * NH2];
__device__ float g_out[BROWS * DOUT];
__device__ float g_normed[BROWS * DOUT];

// ---------------------------------------------------------------------------
// tf32 tensor-core helpers
// ---------------------------------------------------------------------------
__device__ __forceinline__ unsigned to_tf32(float f) {
    unsigned u;
    asm("cvt.rna.tf32.f32 %0, %1;" : "=r"(u) : "f"(f));
    return u;
}
__device__ __forceinline__ void mma_tf32(float d[4], const unsigned a[4],
                                         const unsigned b[2]) {
    asm volatile(
        "mma.sync.aligned.m16n8k8.row.col.f32.tf32.tf32.f32 "
        "{%0,%1,%2,%3}, {%4,%5,%6,%7}, {%8,%9}, {%0,%1,%2,%3};"
        : "+f"(d[0]), "+f"(d[1]), "+f"(d[2]), "+f"(d[3])
        : "r"(a[0]), "r"(a[1]), "r"(a[2]), "r"(a[3]), "r"(b[0]), "r"(b[1]));
}

// ---------------------------------------------------------------------------
// tf32 MMA GEMM (NT): C = tanh(A[M,K] @ W[N,K]^T + b)
// BM=128, BN=64, BK=32, 256 threads, warp grid 4m x 2n (32x32 per warp).
// ---------------------------------------------------------------------------
template<int N, int K>
__device__ __forceinline__ void gemm_tf32_tanh_body(const float* __restrict__ A,
                                                    const float* __restrict__ W,
                                                    const float* __restrict__ bias,
                                                    float* __restrict__ C) {
    __shared__ unsigned As[128 * 36];
    __shared__ unsigned Bs[64 * 36];
    const int tid = threadIdx.x;
    const int w = tid >> 5, lane = tid & 31;
    const int g = lane >> 2, t = lane & 3;
    const int wm = (w & 3) * 32;      // warp m offset in tile
    const int wn = (w >> 2) * 32;     // warp n offset in tile
    const int bm = blockIdx.y * 128, bn = blockIdx.x * 64;

    float d[2][4][4] = {};            // [m frag][n frag][quad]

    for (int k0 = 0; k0 < K; k0 += 32) {
        #pragma unroll
        for (int u = 0; u < 4; u++) {
            const int idx = tid + 256 * u;
            const int row = idx >> 3, c4 = (idx & 7) << 2;
            float4 v = *(const float4*)(A + (size_t)(bm + row) * K + k0 + c4);
            unsigned* s = As + row * 36 + c4;
            s[0] = to_tf32(v.x); s[1] = to_tf32(v.y);
            s[2] = to_tf32(v.z); s[3] = to_tf32(v.w);
        }
        #pragma unroll
        for (int u = 0; u < 2; u++) {
            const int idx = tid + 256 * u;
            const int row = idx >> 3, c4 = (idx & 7) << 2;
            float4 v = *(const float4*)(W + (size_t)(bn + row) * K + k0 + c4);
            unsigned* s = Bs + row * 36 + c4;
            s[0] = to_tf32(v.x); s[1] = to_tf32(v.y);
            s[2] = to_tf32(v.z); s[3] = to_tf32(v.w);
        }
        __syncthreads();

        #pragma unroll
        for (int kk = 0; kk < 4; kk++) {
            const int ka = kk * 8 + t;
            unsigned a[2][4];
            #pragma unroll
            for (int mi = 0; mi < 2; mi++) {
                const unsigned* ab = As + (wm + mi * 16) * 36;
                a[mi][0] = ab[(size_t)g * 36 + ka];
                a[mi][1] = ab[(size_t)(g + 8) * 36 + ka];
                a[mi][2] = ab[(size_t)g * 36 + ka + 4];
                a[mi][3] = ab[(size_t)(g + 8) * 36 + ka + 4];
            }
            #pragma unroll
            for (int ni = 0; ni < 4; ni++) {
                unsigned b[2];
                const unsigned* bb = Bs + (wn + ni * 8 + g) * 36;
                b[0] = bb[ka];
                b[1] = bb[ka + 4];
                mma_tf32(d[0][ni], a[0], b);
                mma_tf32(d[1][ni], a[1], b);
            }
        }
        __syncthreads();
    }

    #pragma unroll
    for (int mi = 0; mi < 2; mi++) {
        #pragma unroll
        for (int ni = 0; ni < 4; ni++) {
            const int colb = bn + wn + ni * 8 + 2 * t;
            const float bb0 = bias[colb], bb1 = bias[colb + 1];
            #pragma unroll
            for (int h = 0; h < 2; h++) {
                const int row = bm + wm + mi * 16 + g + h * 8;
                float* cp = C + (size_t)row * N + colb;
                cp[0] = tanhf(d[mi][ni][2 * h] + bb0);
                cp[1] = tanhf(d[mi][ni][2 * h + 1] + bb1);
            }
        }
    }
}

__global__ void __launch_bounds__(256) gemm_l1(const float* __restrict__ x,
                                               const float* __restrict__ W1,
                                               const float* __restrict__ b1) {
    gemm_tf32_tanh_body<NH1, DIN>(x, W1, b1, g_h1);
}
__global__ void __launch_bounds__(256) gemm_l2(const float* __restrict__ W2,
                                               const float* __restrict__ b2) {
    gemm_tf32_tanh_body<NH2, NH1>(g_h1, W2, b2, g_h2);
}

// ---------------------------------------------------------------------------
// Final linear (no tanh) + per-row L2 norm -> g_out, g_normed.
// Also writes y = -out (cancels the diagonal sure-pass added by fid_mma).
// ---------------------------------------------------------------------------
__global__ void gemm_out_norm(const float* __restrict__ W,
                              const float* __restrict__ bias,
                              float* __restrict__ y) {
    __shared__ float As[16][68];
    __shared__ float Ws[16][68];
    __shared__ float Cs[64][65];
    const int tid = threadIdx.x;
    const int tx = tid & 15, ty = tid >> 4;
    const int bm = blockIdx.x * 64;
    const int lr = tid >> 2;
    const int lc = (tid & 3) << 2;

    const float* Ag = g_h2 + (size_t)(bm + lr) * 256 + lc;
    const float* Wg = W + (size_t)lr * 256 + lc;   // W3 is [64,256]

    float acc[4][4] = {};
    for (int k0 = 0; k0 < 256; k0 += 16) {
        float4 av = *(const float4*)(Ag + k0);
        float4 wv = *(const float4*)(Wg + k0);
        As[lc + 0][lr] = av.x; As[lc + 1][lr] = av.y;
        As[lc + 2][lr] = av.z; As[lc + 3][lr] = av.w;
        Ws[lc + 0][lr] = wv.x; Ws[lc + 1][lr] = wv.y;
        Ws[lc + 2][lr] = wv.z; Ws[lc + 3][lr] = wv.w;
        __syncthreads();
        #pragma unroll
        for (int k = 0; k < 16; k++) {
            float4 a4 = *(const float4*)&As[k][ty << 2];
            float4 w4 = *(const float4*)&Ws[k][tx << 2];
            float a[4] = {a4.x, a4.y, a4.z, a4.w};
            float ww[4] = {w4.x, w4.y, w4.z, w4.w};
            #pragma unroll
            for (int i2 = 0; i2 < 4; i2++)
                #pragma unroll
                for (int j2 = 0; j2 < 4; j2++)
                    acc[i2][j2] = fmaf(a[i2], ww[j2], acc[i2][j2]);
        }
        __syncthreads();
    }
    #pragma unroll
    for (int i2 = 0; i2 < 4; i2++)
        #pragma unroll
        for (int j2 = 0; j2 < 4; j2++)
            Cs[(ty << 2) + i2][(tx << 2) + j2] = acc[i2][j2] + bias[(tx << 2) + j2];
    __syncthreads();

    const int warp = tid >> 5, lane = tid & 31;
    #pragma unroll
    for (int r8 = 0; r8 < 8; r8++) {
        const int r = warp * 8 + r8;
        const float v0 = Cs[r][lane];
        const float v1 = Cs[r][lane + 32];
        float s = v0 * v0 + v1 * v1;
        #pragma unroll
        for (int off = 16; off; off >>= 1)
            s += __shfl_xor_sync(0xffffffffu, s, off);
        const float inv = 1.0f / (sqrtf(s) + 1e-12f);
        const size_t base = (size_t)(bm + r) * 64;
        g_out[base + lane]        = v0;
        g_out[base + lane + 32]   = v1;
        g_normed[base + lane]      = v0 * inv;
        g_normed[base + lane + 32] = v1 * inv;
        y[base + lane]      = -v0;
        y[base + lane + 32] = -v1;
    }
}

// ---------------------------------------------------------------------------
// Fidelity via tf32 MMA + fp32 guard-band recheck.
// sn holds PRE-CONVERTED tf32 in fragment-paired layout (a permutation of the
// 64 columns within each row):
//   word(row, k) at row*SNS + (k>>3)*8 + (k&3)*2 + ((k>>2)&1)
// so the b-frag pair (k, k+4) is one aligned LDS.64. Inner loop per kk:
// 2 LDS.64 + 2 MMA (was 4 LDS.32 + 4 CVT + 2 MMA).
// ---------------------------------------------------------------------------
__global__ void __launch_bounds__(256) fid_mma(float* __restrict__ y) {
    __shared__ unsigned sn[FJT * SNS];   // tf32 bits, paired layout
    __shared__ float so[FJT * 64];       // out_j (fp32)
    const int tid = threadIdx.x;
    const int w = tid >> 5, lane = tid & 31;
    const int g = lane >> 2, t = lane & 3;
    const int i0 = blockIdx.x * 128 + w * 16;   // warp's 16 i-rows

    // A fragments: m16 x k64 (8 k-steps), loaded once from gmem
    unsigned a[8][4];
    {
        const float* base = g_normed + (size_t)i0 * 64;
        #pragma unroll
        for (int kk = 0; kk < 8; kk++) {
            a[kk][0] = to_tf32(base[(size_t)g * 64 + kk * 8 + t]);
            a[kk][1] = to_tf32(base[(size_t)(g + 8) * 64 + kk * 8 + t]);
            a[kk][2] = to_tf32(base[(size_t)g * 64 + kk * 8 + t + 4]);
            a[kk][3] = to_tf32(base[(size_t)(g + 8) * 64 + kk * 8 + t + 4]);
        }
    }

    const int jb0 = blockIdx.y * FSEG;
    for (int jc = 0; jc < FSEG; jc += FJT) {
        const int jb = jb0 + jc;
        {   // cooperative chunk load; sn gets cvt+permute, so is a raw copy
            const float4* gn = (const float4*)(g_normed + (size_t)jb * 64);
            const float4* go = (const float4*)(g_out + (size_t)jb * 64);
            #pragma unroll
            for (int u = 0; u < 4; u++) {
                const int idx = tid + 256 * u;          // 0..1023 float4s
                const int row = idx >> 4, q = idx & 15; // q: float4 index in row
                float4 v = gn[idx];
                // cols 4q+e -> dest offset (q>>1)*8 + e*2 + (q&1), e=0..3
                unsigned* s = sn + row * SNS + (q >> 1) * 8 + (q & 1);
                s[0] = to_tf32(v.x);
                s[2] = to_tf32(v.y);
                s[4] = to_tf32(v.z);
                s[6] = to_tf32(v.w);
                ((float4*)so)[idx] = go[idx];
            }
        }
        __syncthreads();

        #pragma unroll
        for (int np = 0; np < 4; np++) {
            const int n0 = np * 16;
            float d0[4] = {0.f, 0.f, 0.f, 0.f};
            float d1[4] = {0.f, 0.f, 0.f, 0.f};
            const unsigned* r0 = sn + (n0 + g) * SNS + t * 2;
            const unsigned* r1 = sn + (n0 + 8 + g) * SNS + t * 2;
            #pragma unroll
            for (int kk = 0; kk < 8; kk++) {
                uint2 b0 = *(const uint2*)(r0 + kk * 8);
                uint2 b1 = *(const uint2*)(r1 + kk * 8);
                mma_tf32(d0, a[kk], &b0.x);
                mma_tf32(d1, a[kk], &b1.x);
            }
            #pragma unroll
            for (int half = 0; half < 2; half++) {
                const float* dd = half ? d1 : d0;
                const int nb = n0 + half * 8;
                #pragma unroll
                for (int q = 0; q < 4; q++) {
                    const float ad = fabsf(dd[q]);
                    if (ad < S_LO) continue;            // common case
                    const int ri = i0 + g + (q >> 1) * 8;
                    const int jl = nb + 2 * t + (q & 1);
                    bool pass = true;
                    if (ad < S_HI) {                    // ambiguous: fp32 recheck
                        const float* ni = g_normed + (size_t)ri * 64;
                        const float* nj = g_normed + (size_t)(jb + jl) * 64;
                        float s = 0.f;
                        #pragma unroll 8
                        for (int k = 0; k < 64; k++) s = fmaf(ni[k], nj[k], s);
                        pass = (s * s >= 0.9f);
                    }
                    if (pass) {
                        const float* oj = so + jl * 64;
                        float* yp = y + (size_t)ri * 64;
                        #pragma unroll 8
                        for (int u = 0; u < 64; u++) atomicAdd(yp + u, oj[u]);
                    }
                }
            }
        }
        __syncthreads();
    }
}

// ---------------------------------------------------------------------------
extern "C" void kernel_launch(void* const* d_in, const int* in_sizes, int n_in,
                              void* d_out, int out_size) {
    const float* x  = (const float*)d_in[0];
    const float* W1 = (const float*)d_in[1];
    const float* b1 = (const float*)d_in[2];
    const float* W2 = (const float*)d_in[3];
    const float* b2 = (const float*)d_in[4];
    const float* W3 = (const float*)d_in[5];
    const float* b3 = (const float*)d_in[6];
    float* y = (float*)d_out;

    gemm_l1<<<dim3(NH1 / 64, BROWS / 128), 256>>>(x, W1, b1);
    gemm_l2<<<dim3(NH2 / 64, BROWS / 128), 256>>>(W2, b2);
    gemm_out_norm<<<BROWS / 64, 256>>>(W3, b3, y);
    fid_mma<<<dim3(BROWS / 128, FNS), 256>>>(y);
}

// round 16
// speedup vs baseline: 7.5415x; 1.0514x over previous
#include <cuda_runtime.h>
#include <cuda_bf16.h>

// Problem dims (fixed by reference)
#define BROWS 8192
#define DIN   256
#define NH1   512
#define NH2   256
#define DOUT  64

// Fidelity threshold: pass iff dot^2 >= 0.9  <=>  |dot| >= sqrt(0.9)=0.948683
// bf16 guard band: |dot_bf16 - dot_fp32| <= 2*2^-9 * sum|a_k b_k| <= 2^-8 = 3.9e-3
#define S_LO 0.9437f   // sure-fail below
#define S_HI 0.9537f   // sure-pass above
#define FNS  8                 // j-range splits
#define FSEG (BROWS / FNS)     // 1024
#define FJT  64                // j-chunk rows in smem
#define SNSB 40                // sn row stride in words (32 data + 8 pad; ==8 mod 32)

// Scratch (no cudaMalloc allowed)
__device__ float g_h1[BROWS * NH1];
__device__ float g_h2[BROWS * NH2];
__device__ float g_out[BROWS * DOUT];
__device__ float g_normed[BROWS * DOUT];

// ---------------------------------------------------------------------------
// tensor-core helpers
// ---------------------------------------------------------------------------
__device__ __forceinline__ unsigned to_tf32(float f) {
    unsigned u;
    asm("cvt.rna.tf32.f32 %0, %1;" : "=r"(u) : "f"(f));
    return u;
}
__device__ __forceinline__ void mma_tf32(float d[4], const unsigned a[4],
                                         const unsigned b[2]) {
    asm volatile(
        "mma.sync.aligned.m16n8k8.row.col.f32.tf32.tf32.f32 "
        "{%0,%1,%2,%3}, {%4,%5,%6,%7}, {%8,%9}, {%0,%1,%2,%3};"
        : "+f"(d[0]), "+f"(d[1]), "+f"(d[2]), "+f"(d[3])
        : "r"(a[0]), "r"(a[1]), "r"(a[2]), "r"(a[3]), "r"(b[0]), "r"(b[1]));
}
__device__ __forceinline__ unsigned pack_bf16(float lo, float hi) {
    __nv_bfloat162 h = __floats2bfloat162_rn(lo, hi);
    return *(unsigned*)&h;
}
__device__ __forceinline__ void mma_bf16(float d[4], const unsigned a[4],
                                         const unsigned b0, const unsigned b1) {
    asm volatile(
        "mma.sync.aligned.m16n8k16.row.col.f32.bf16.bf16.f32 "
        "{%0,%1,%2,%3}, {%4,%5,%6,%7}, {%8,%9}, {%0,%1,%2,%3};"
        : "+f"(d[0]), "+f"(d[1]), "+f"(d[2]), "+f"(d[3])
        : "r"(a[0]), "r"(a[1]), "r"(a[2]), "r"(a[3]), "r"(b0), "r"(b1));
}

// ---------------------------------------------------------------------------
// tf32 MMA GEMM (NT): C = tanh(A[M,K] @ W[N,K]^T + b)
// BM=128, BN=64, BK=32, 256 threads, warp grid 4m x 2n (32x32 per warp).
// ---------------------------------------------------------------------------
template<int N, int K>
__device__ __forceinline__ void gemm_tf32_tanh_body(const float* __restrict__ A,
                                                    const float* __restrict__ W,
                                                    const float* __restrict__ bias,
                                                    float* __restrict__ C) {
    __shared__ unsigned As[128 * 36];
    __shared__ unsigned Bs[64 * 36];
    const int tid = threadIdx.x;
    const int w = tid >> 5, lane = tid & 31;
    const int g = lane >> 2, t = lane & 3;
    const int wm = (w & 3) * 32;
    const int wn = (w >> 2) * 32;
    const int bm = blockIdx.y * 128, bn = blockIdx.x * 64;

    float d[2][4][4] = {};

    for (int k0 = 0; k0 < K; k0 += 32) {
        #pragma unroll
        for (int u = 0; u < 4; u++) {
            const int idx = tid + 256 * u;
            const int row = idx >> 3, c4 = (idx & 7) << 2;
            float4 v = *(const float4*)(A + (size_t)(bm + row) * K + k0 + c4);
            unsigned* s = As + row * 36 + c4;
            s[0] = to_tf32(v.x); s[1] = to_tf32(v.y);
            s[2] = to_tf32(v.z); s[3] = to_tf32(v.w);
        }
        #pragma unroll
        for (int u = 0; u < 2; u++) {
            const int idx = tid + 256 * u;
            const int row = idx >> 3, c4 = (idx & 7) << 2;
            float4 v = *(const float4*)(W + (size_t)(bn + row) * K + k0 + c4);
            unsigned* s = Bs + row * 36 + c4;
            s[0] = to_tf32(v.x); s[1] = to_tf32(v.y);
            s[2] = to_tf32(v.z); s[3] = to_tf32(v.w);
        }
        __syncthreads();

        #pragma unroll
        for (int kk = 0; kk < 4; kk++) {
            const int ka = kk * 8 + t;
            unsigned a[2][4];
            #pragma unroll
            for (int mi = 0; mi < 2; mi++) {
                const unsigned* ab = As + (wm + mi * 16) * 36;
                a[mi][0] = ab[(size_t)g * 36 + ka];
                a[mi][1] = ab[(size_t)(g + 8) * 36 + ka];
                a[mi][2] = ab[(size_t)g * 36 + ka + 4];
                a[mi][3] = ab[(size_t)(g + 8) * 36 + ka + 4];
            }
            #pragma unroll
            for (int ni = 0; ni < 4; ni++) {
                unsigned b[2];
                const unsigned* bb = Bs + (wn + ni * 8 + g) * 36;
                b[0] = bb[ka];
                b[1] = bb[ka + 4];
                mma_tf32(d[0][ni], a[0], b);
                mma_tf32(d[1][ni], a[1], b);
            }
        }
        __syncthreads();
    }

    #pragma unroll
    for (int mi = 0; mi < 2; mi++) {
        #pragma unroll
        for (int ni = 0; ni < 4; ni++) {
            const int colb = bn + wn + ni * 8 + 2 * t;
            const float bb0 = bias[colb], bb1 = bias[colb + 1];
            #pragma unroll
            for (int h = 0; h < 2; h++) {
                const int row = bm + wm + mi * 16 + g + h * 8;
                float* cp = C + (size_t)row * N + colb;
                cp[0] = tanhf(d[mi][ni][2 * h] + bb0);
                cp[1] = tanhf(d[mi][ni][2 * h + 1] + bb1);
            }
        }
    }
}

__global__ void __launch_bounds__(256) gemm_l1(const float* __restrict__ x,
                                               const float* __restrict__ W1,
                                               const float* __restrict__ b1) {
    gemm_tf32_tanh_body<NH1, DIN>(x, W1, b1, g_h1);
}
__global__ void __launch_bounds__(256) gemm_l2(const float* __restrict__ W2,
                                               const float* __restrict__ b2) {
    gemm_tf32_tanh_body<NH2, NH1>(g_h1, W2, b2, g_h2);
}

// ---------------------------------------------------------------------------
// Final linear (no tanh) + per-row L2 norm -> g_out, g_normed.
// Also writes y = -out (cancels the diagonal sure-pass added by fid_mma).
// ---------------------------------------------------------------------------
__global__ void gemm_out_norm(const float* __restrict__ W,
                              const float* __restrict__ bias,
                              float* __restrict__ y) {
    __shared__ float As[16][68];
    __shared__ float Ws[16][68];
    __shared__ float Cs[64][65];
    const int tid = threadIdx.x;
    const int tx = tid & 15, ty = tid >> 4;
    const int bm = blockIdx.x * 64;
    const int lr = tid >> 2;
    const int lc = (tid & 3) << 2;

    const float* Ag = g_h2 + (size_t)(bm + lr) * 256 + lc;
    const float* Wg = W + (size_t)lr * 256 + lc;   // W3 is [64,256]

    float acc[4][4] = {};
    for (int k0 = 0; k0 < 256; k0 += 16) {
        float4 av = *(const float4*)(Ag + k0);
        float4 wv = *(const float4*)(Wg + k0);
        As[lc + 0][lr] = av.x; As[lc + 1][lr] = av.y;
        As[lc + 2][lr] = av.z; As[lc + 3][lr] = av.w;
        Ws[lc + 0][lr] = wv.x; Ws[lc + 1][lr] = wv.y;
        Ws[lc + 2][lr] = wv.z; Ws[lc + 3][lr] = wv.w;
        __syncthreads();
        #pragma unroll
        for (int k = 0; k < 16; k++) {
            float4 a4 = *(const float4*)&As[k][ty << 2];
            float4 w4 = *(const float4*)&Ws[k][tx << 2];
            float a[4] = {a4.x, a4.y, a4.z, a4.w};
            float ww[4] = {w4.x, w4.y, w4.z, w4.w};
            #pragma unroll
            for (int i2 = 0; i2 < 4; i2++)
                #pragma unroll
                for (int j2 = 0; j2 < 4; j2++)
                    acc[i2][j2] = fmaf(a[i2], ww[j2], acc[i2][j2]);
        }
        __syncthreads();
    }
    #pragma unroll
    for (int i2 = 0; i2 < 4; i2++)
        #pragma unroll
        for (int j2 = 0; j2 < 4; j2++)
            Cs[(ty << 2) + i2][(tx << 2) + j2] = acc[i2][j2] + bias[(tx << 2) + j2];
    __syncthreads();

    const int warp = tid >> 5, lane = tid & 31;
    #pragma unroll
    for (int r8 = 0; r8 < 8; r8++) {
        const int r = warp * 8 + r8;
        const float v0 = Cs[r][lane];
        const float v1 = Cs[r][lane + 32];
        float s = v0 * v0 + v1 * v1;
        #pragma unroll
        for (int off = 16; off; off >>= 1)
            s += __shfl_xor_sync(0xffffffffu, s, off);
        const float inv = 1.0f / (sqrtf(s) + 1e-12f);
        const size_t base = (size_t)(bm + r) * 64;
        g_out[base + lane]        = v0;
        g_out[base + lane + 32]   = v1;
        g_normed[base + lane]      = v0 * inv;
        g_normed[base + lane + 32] = v1 * inv;
        y[base + lane]      = -v0;
        y[base + lane + 32] = -v1;
    }
}

// ---------------------------------------------------------------------------
// Fidelity via bf16 m16n8k16 MMA + fp32 guard-band recheck.
// 128 threads (4 warps); each warp covers m32 (2 m-frags) -> block = 128 i.
// sn: bf16x2 words, fragment-paired layout. Word for col-pair p (cols 2p,2p+1)
// at row*SNSB + (p>>3)*8 + (p&3)*2 + ((p>>2)&1); the b-frag pair (p, p+4) is
// one aligned LDS.64. Per k16-step: 2 LDS.64 + 4 MMA (4 independent chains).
// ---------------------------------------------------------------------------
__global__ void __launch_bounds__(128) fid_mma(float* __restrict__ y) {
    __shared__ unsigned sn[FJT * SNSB];  // bf16x2 words, paired layout
    __shared__ float so[FJT * 64];       // out_j (fp32)
    const int tid = threadIdx.x;
    const int w = tid >> 5, lane = tid & 31;
    const int g = lane >> 2, t = lane & 3;
    const int i0 = blockIdx.x * 128 + w * 32;   // warp's 32 i-rows

    // A fragments: 2 m16-frags x 4 k16-steps, packed bf16x2, loaded once
    unsigned a[2][4][4];
    #pragma unroll
    for (int mi = 0; mi < 2; mi++) {
        const float* base = g_normed + (size_t)(i0 + mi * 16) * 64;
        #pragma unroll
        for (int kk = 0; kk < 4; kk++) {
            const int kb = kk * 16 + 2 * t;
            float2 v00 = *(const float2*)(base + (size_t)g * 64 + kb);
            float2 v10 = *(const float2*)(base + (size_t)(g + 8) * 64 + kb);
            float2 v01 = *(const float2*)(base + (size_t)g * 64 + kb + 8);
            float2 v11 = *(const float2*)(base + (size_t)(g + 8) * 64 + kb + 8);
            a[mi][kk][0] = pack_bf16(v00.x, v00.y);
            a[mi][kk][1] = pack_bf16(v10.x, v10.y);
            a[mi][kk][2] = pack_bf16(v01.x, v01.y);
            a[mi][kk][3] = pack_bf16(v11.x, v11.y);
        }
    }

    const int jb0 = blockIdx.y * FSEG;
    for (int jc = 0; jc < FSEG; jc += FJT) {
        const int jb = jb0 + jc;
        {   // cooperative chunk load: cvt+pack normed into sn, raw copy out
            const float4* gn = (const float4*)(g_normed + (size_t)jb * 64);
            const float4* go = (const float4*)(g_out + (size_t)jb * 64);
            #pragma unroll
            for (int u = 0; u < 8; u++) {
                const int idx = tid + 128 * u;          // 0..1023 float4s
                const int row = idx >> 4, q = idx & 15; // float4 index in row
                float4 v = gn[idx];
                // float4 q covers col-pairs p0=2q, p1=2q+1
                const int p0 = 2 * q, p1 = 2 * q + 1;
                unsigned* s = sn + row * SNSB;
                s[(p0 >> 3) * 8 + (p0 & 3) * 2 + ((p0 >> 2) & 1)] = pack_bf16(v.x, v.y);
                s[(p1 >> 3) * 8 + (p1 & 3) * 2 + ((p1 >> 2) & 1)] = pack_bf16(v.z, v.w);
                ((float4*)so)[idx] = go[idx];
            }
        }
        __syncthreads();

        #pragma unroll
        for (int np = 0; np < 4; np++) {
            const int n0 = np * 16;
            float d[2][2][4] = {};
            const unsigned* r0 = sn + (n0 + g) * SNSB + t * 2;
            const unsigned* r1 = sn + (n0 + 8 + g) * SNSB + t * 2;
            #pragma unroll
            for (int kk = 0; kk < 4; kk++) {
                uint2 b0 = *(const uint2*)(r0 + kk * 8);
                uint2 b1 = *(const uint2*)(r1 + kk * 8);
                mma_bf16(d[0][0], a[0][kk], b0.x, b0.y);
                mma_bf16(d[0][1], a[0][kk], b1.x, b1.y);
                mma_bf16(d[1][0], a[1][kk], b0.x, b0.y);
                mma_bf16(d[1][1], a[1][kk], b1.x, b1.y);
            }
            #pragma unroll
            for (int mi = 0; mi < 2; mi++) {
                #pragma unroll
                for (int nh = 0; nh < 2; nh++) {
                    const float* dd = d[mi][nh];
                    const int nb = n0 + nh * 8;
                    #pragma unroll
                    for (int q = 0; q < 4; q++) {
                        const float ad = fabsf(dd[q]);
                        if (ad < S_LO) continue;        // common case
                        const int ri = i0 + mi * 16 + g + (q >> 1) * 8;
                        const int jl = nb + 2 * t + (q & 1);
                        bool pass = true;
                        if (ad < S_HI) {                // ambiguous: fp32 recheck
                            const float* ni = g_normed + (size_t)ri * 64;
                            const float* nj = g_normed + (size_t)(jb + jl) * 64;
                            float s = 0.f;
                            #pragma unroll 8
                            for (int k = 0; k < 64; k++) s = fmaf(ni[k], nj[k], s);
                            pass = (s * s >= 0.9f);
                        }
                        if (pass) {
                            const float* oj = so + jl * 64;
                            float* yp = y + (size_t)ri * 64;
                            #pragma unroll 8
                            for (int u = 0; u < 64; u++) atomicAdd(yp + u, oj[u]);
                        }
                    }
                }
            }
        }
        __syncthreads();
    }
}

// ---------------------------------------------------------------------------
extern "C" void kernel_launch(void* const* d_in, const int* in_sizes, int n_in,
                              void* d_out, int out_size) {
    const float* x  = (const float*)d_in[0];
    const float* W1 = (const float*)d_in[1];
    const float* b1 = (const float*)d_in[2];
    const float* W2 = (const float*)d_in[3];
    const float* b2 = (const float*)d_in[4];
    const float* W3 = (const float*)d_in[5];
    const float* b3 = (const float*)d_in[6];
    float* y = (float*)d_out;

    gemm_l1<<<dim3(NH1 / 64, BROWS / 128), 256>>>(x, W1, b1);
    gemm_l2<<<dim3(NH2 / 64, BROWS / 128), 256>>>(W2, b2);
    gemm_out_norm<<<BROWS / 64, 256>>>(W3, b3, y);
    fid_mma<<<dim3(BROWS / 128, FNS), 128>>>(y);
}